// round 15
// baseline (speedup 1.0000x reference)
#include <cuda_runtime.h>
#include <cuda_bf16.h>
#include <cstdint>

#define NNODES 100000
#define NPAD 100096                     // padded rows (multiple of 128)
#define EEDGES 1600000
#define FF 32
#define HH 128
#define LLAYERS 4
#define GG 64
#define H3 384
#define SCANB 512
#define NSCAN ((NNODES + SCANB - 1) / SCANB)   // 196

// ---------------- scratch (device globals; no allocation) ----------------
__device__ float g_h[(size_t)NNODES * HH];
__device__ float g_grz[(size_t)NNODES * 256];   // combined r,z pre-activations (gi+gh)
__device__ float g_ghn[(size_t)NNODES * HH];    // h_n
__device__ float g_outv[NNODES];
__device__ float g_gsum[GG];
__device__ float g_gcnt[GG];
__device__ int   g_src[EEDGES];
__device__ int   g_dst[EEDGES];
__device__ int   g_batch[NNODES];
__device__ int   g_edge_i32;
__device__ int   g_batch_i32;
// CSR
__device__ int   g_deg[NNODES];
__device__ int   g_cur[NNODES];
__device__ int   g_off[NNODES + 1];
__device__ int   g_part[NSCAN];
__device__ int   g_part2[NSCAN];
__device__ int   g_csr_src[EEDGES];

// pre-split bf16 A operands (hi/lo planes), padded rows
__device__ unsigned short g_ah[(size_t)NPAD * HH];   // agg hi
__device__ unsigned short g_al[(size_t)NPAD * HH];   // agg lo
__device__ unsigned short g_xh[(size_t)NPAD * HH];   // h hi
__device__ unsigned short g_xl[(size_t)NPAD * HH];   // h lo

// bf16 split weights (hi/lo), n-major:
// rz combined: [l][col 0..255][k 0..255]; k<128 -> W_comb_rz, k>=128 -> w_hh_rz
__device__ unsigned short g_rz_h[(size_t)LLAYERS * 256 * 256];
__device__ unsigned short g_rz_l[(size_t)LLAYERS * 256 * 256];
// n gates: i_n weights [l][128][128], h_n weights [128][128]
__device__ unsigned short g_cn_h[(size_t)LLAYERS * HH * HH];
__device__ unsigned short g_cn_l[(size_t)LLAYERS * HH * HH];
__device__ unsigned short g_hn_h[HH * HH];
__device__ unsigned short g_hn_l[HH * HH];

// ---------------- math helpers ----------------
__device__ __forceinline__ float sigf(float x) { return 1.f / (1.f + __expf(-x)); }
__device__ __forceinline__ float tanhfast(float x) {
    float ax = fabsf(x);
    float e = __expf(-2.f * ax);
    float t = (1.f - e) / (1.f + e);
    return copysignf(t, x);
}
__device__ __forceinline__ void fma2(unsigned long long& d, unsigned long long a,
                                     unsigned long long b) {
    asm("fma.rn.f32x2 %0, %1, %2, %3;" : "=l"(d) : "l"(a), "l"(b), "l"(d));
}
__device__ __forceinline__ unsigned long long pack_dup(float x) {
    unsigned long long r;
    asm("mov.b64 %0, {%1, %1};" : "=l"(r) : "f"(x));
    return r;
}
__device__ __forceinline__ float2 unpack2(unsigned long long v) {
    float2 r;
    asm("mov.b64 {%0, %1}, %2;" : "=f"(r.x), "=f"(r.y) : "l"(v));
    return r;
}
__device__ __forceinline__ void split1(float a, unsigned short& h, unsigned short& l) {
    __nv_bfloat16 ha = __float2bfloat16_rn(a);
    float ra = a - __bfloat162float(ha);
    __nv_bfloat16 la = __float2bfloat16_rn(ra);
    h = __bfloat16_as_ushort(ha);
    l = __bfloat16_as_ushort(la);
}
__device__ __forceinline__ void split2(float a, float b, unsigned& h, unsigned& l) {
    unsigned short ha, la, hb, lb;
    split1(a, ha, la);
    split1(b, hb, lb);
    h = (unsigned)ha | ((unsigned)hb << 16);
    l = (unsigned)la | ((unsigned)lb << 16);
}
__device__ __forceinline__ void split4(float4 v, uint2& h, uint2& l) {
    split2(v.x, v.y, h.x, l.x);
    split2(v.z, v.w, h.y, l.y);
}
__device__ __forceinline__ void ldm4(unsigned r[4], uint32_t addr) {
    asm volatile("ldmatrix.sync.aligned.m8n8.x4.shared.b16 {%0,%1,%2,%3}, [%4];\n"
                 : "=r"(r[0]), "=r"(r[1]), "=r"(r[2]), "=r"(r[3])
                 : "r"(addr));
}
__device__ __forceinline__ void mma16816(float* c, const unsigned a[4],
                                         unsigned b0, unsigned b1) {
    asm("mma.sync.aligned.m16n8k16.row.col.f32.bf16.bf16.f32 "
        "{%0,%1,%2,%3}, {%4,%5,%6,%7}, {%8,%9}, {%0,%1,%2,%3};\n"
        : "+f"(c[0]), "+f"(c[1]), "+f"(c[2]), "+f"(c[3])
        : "r"(a[0]), "r"(a[1]), "r"(a[2]), "r"(a[3]), "r"(b0), "r"(b1));
}

// ---------------- setup kernels ----------------
__global__ void zero_init_kernel() {
    int i = blockIdx.x * 256 + threadIdx.x;
    if (i < NNODES) { g_deg[i] = 0; g_cur[i] = 0; }
    if (i < GG) { g_gsum[i] = 0.f; g_gcnt[i] = 0.f; }
    if (i == 0) { g_edge_i32 = 0; g_batch_i32 = 0; }
}
__global__ void detect_kernel(const unsigned int* __restrict__ pe,
                              const unsigned int* __restrict__ pb) {
    int which = blockIdx.y;
    const unsigned int* p = which ? pb : pe;
    long long nwords = which ? (long long)NNODES : 2LL * EEDGES;
    long long i = 1 + 2LL * (blockIdx.x * (long long)blockDim.x + threadIdx.x);
    long long stride = 2LL * gridDim.x * blockDim.x;
    int found = 0;
    for (; i < nwords; i += stride)
        if (p[i]) { found = 1; break; }
    if (found) { if (which == 0) g_edge_i32 = 1; else g_batch_i32 = 1; }
}
__global__ void convert_edges_kernel(const void* __restrict__ e) {
    int i = blockIdx.x * 256 + threadIdx.x;
    if (i >= EEDGES) return;
    int s, d;
    if (g_edge_i32) {
        const int* p = (const int*)e;
        s = __ldcs(p + i); d = __ldcs(p + EEDGES + i);
    } else {
        const long long* p = (const long long*)e;
        s = (int)__ldcs(p + i); d = (int)__ldcs(p + EEDGES + i);
    }
    g_src[i] = s;
    g_dst[i] = d;
    atomicAdd(&g_deg[d], 1);
}
__global__ void convert_batch_kernel(const void* __restrict__ b) {
    int i = blockIdx.x * 256 + threadIdx.x;
    if (i >= NNODES) return;
    if (g_batch_i32) g_batch[i] = ((const int*)b)[i];
    else             g_batch[i] = (int)((const long long*)b)[i];
}

// ---------------- scan (exclusive prefix over degrees) ----------------
__global__ void scan1_kernel() {
    __shared__ int s[SCANB];
    int t = threadIdx.x;
    int i = blockIdx.x * SCANB + t;
    int v = (i < NNODES) ? g_deg[i] : 0;
    s[t] = v;
    __syncthreads();
#pragma unroll
    for (int o = 1; o < SCANB; o <<= 1) {
        int x = (t >= o) ? s[t - o] : 0;
        __syncthreads();
        s[t] += x;
        __syncthreads();
    }
    if (i < NNODES) g_off[i] = s[t] - v;
    if (t == SCANB - 1) g_part[blockIdx.x] = s[t];
}
__global__ void scan2_kernel() {
    __shared__ int s[256];
    int t = threadIdx.x;
    int v = (t < NSCAN) ? g_part[t] : 0;
    s[t] = v;
    __syncthreads();
#pragma unroll
    for (int o = 1; o < 256; o <<= 1) {
        int x = (t >= o) ? s[t - o] : 0;
        __syncthreads();
        s[t] += x;
        __syncthreads();
    }
    if (t < NSCAN) g_part2[t] = s[t] - v;
}
__global__ void scan3_kernel() {
    int i = blockIdx.x * SCANB + threadIdx.x;
    if (i < NNODES) g_off[i] += g_part2[blockIdx.x];
    if (i == 0) g_off[NNODES] = EEDGES;
}
__global__ void fill_csr_kernel() {
    int i = blockIdx.x * 256 + threadIdx.x;
    if (i >= EEDGES) return;
    int d = g_dst[i];
    int p = atomicAdd(&g_cur[d], 1);
    g_csr_src[g_off[d] + p] = g_src[i];
}

// ---------------- fold GEMM: W_comb = w_ih x conv_w; epilogue splits + routes ----------------
#define FOLD_SMEM (2 * 128 * 128 * 4)
__global__ void fold_gemm_kernel(const float* __restrict__ A,
                                 const float* __restrict__ Bbase) {
    const float* B = Bbase + (size_t)blockIdx.z * HH * HH;
    const int l = blockIdx.z;
    extern __shared__ float smf[];
    float* aT = smf;
    float* ws = smf + 128 * 128;
    int m0 = blockIdx.x * 128;
    int tid = threadIdx.x;
    {
        int i = tid >> 1;
        int kq0 = (tid & 1) * 16;
        const float4* Ar = (const float4*)(A + (size_t)(m0 + i) * 128);
#pragma unroll
        for (int q = 0; q < 16; q++) {
            int k4 = kq0 + q;
            float4 v = Ar[k4];
            aT[(k4 * 4 + 0) * 128 + i] = v.x; aT[(k4 * 4 + 1) * 128 + i] = v.y;
            aT[(k4 * 4 + 2) * 128 + i] = v.z; aT[(k4 * 4 + 3) * 128 + i] = v.w;
        }
    }
    {
        int k = tid >> 1;
        int kq0 = (tid & 1) * 16;
        const float4* Br = (const float4*)(B + (size_t)k * 128);
#pragma unroll
        for (int q = 0; q < 16; q++) {
            int k4 = kq0 + q;
            float4 v = Br[k4];
            ws[(k4 * 4 + 0) * 128 + k] = v.x; ws[(k4 * 4 + 1) * 128 + k] = v.y;
            ws[(k4 * 4 + 2) * 128 + k] = v.z; ws[(k4 * 4 + 3) * 128 + k] = v.w;
        }
    }
    __syncthreads();

    int tx = tid & 15, ty = tid >> 4;
    unsigned long long acc[8][4];
#pragma unroll
    for (int i = 0; i < 8; i++)
#pragma unroll
        for (int j = 0; j < 4; j++) acc[i][j] = 0ull;

    const float* aBase = aT + ty * 8;
    const float* bBase = ws + tx * 8;
#pragma unroll 4
    for (int k = 0; k < 128; k++) {
        float4 a0 = *(const float4*)(aBase + k * 128);
        float4 a1 = *(const float4*)(aBase + k * 128 + 4);
        const unsigned long long* bp = (const unsigned long long*)(bBase + k * 128);
        unsigned long long b0 = bp[0], b1 = bp[1], b2 = bp[2], b3 = bp[3];
        float av[8] = {a0.x, a0.y, a0.z, a0.w, a1.x, a1.y, a1.z, a1.w};
#pragma unroll
        for (int i = 0; i < 8; i++) {
            unsigned long long a2 = pack_dup(av[i]);
            fma2(acc[i][0], a2, b0); fma2(acc[i][1], a2, b1);
            fma2(acc[i][2], a2, b2); fma2(acc[i][3], a2, b3);
        }
    }
#pragma unroll
    for (int i = 0; i < 8; i++) {
        int row = m0 + ty * 8 + i;          // gate-output index 0..383
        float vv[8];
        float2 v0 = unpack2(acc[i][0]), v1 = unpack2(acc[i][1]);
        float2 v2 = unpack2(acc[i][2]), v3 = unpack2(acc[i][3]);
        vv[0] = v0.x; vv[1] = v0.y; vv[2] = v1.x; vv[3] = v1.y;
        vv[4] = v2.x; vv[5] = v2.y; vv[6] = v3.x; vv[7] = v3.y;
        unsigned short hs[8], ls[8];
#pragma unroll
        for (int q = 0; q < 8; q++) split1(vv[q], hs[q], ls[q]);
        if (row < 256) {                    // r,z gates -> rz combined, k slot [0,128)
            size_t off = ((size_t)l * 256 + row) * 256 + tx * 8;
#pragma unroll
            for (int q = 0; q < 8; q++) { g_rz_h[off + q] = hs[q]; g_rz_l[off + q] = ls[q]; }
        } else {                            // n gate -> cn
            size_t off = ((size_t)l * HH + (row - 256)) * HH + tx * 8;
#pragma unroll
            for (int q = 0; q < 8; q++) { g_cn_h[off + q] = hs[q]; g_cn_l[off + q] = ls[q]; }
        }
    }
}

__global__ void whh_split_kernel(const float* __restrict__ whh) {
    int idx = blockIdx.x * 256 + threadIdx.x;
    if (idx >= H3 * HH) return;
    int o = idx >> 7;
    int k = idx & 127;
    unsigned short h, lo;
    split1(whh[idx], h, lo);
    if (o < 256) {
#pragma unroll
        for (int l = 0; l < LLAYERS; l++) {
            size_t off = ((size_t)l * 256 + o) * 256 + 128 + k;
            g_rz_h[off] = h; g_rz_l[off] = lo;
        }
    } else {
        size_t off = (size_t)(o - 256) * HH + k;
        g_hn_h[off] = h; g_hn_l[off] = lo;
    }
}

// ---------------- embed: h = sigmoid(x @ W0^T); writes h fp32 + planes ----------------
__global__ void embed_kernel(const float* __restrict__ x, const float* __restrict__ W0,
                             float* __restrict__ out_emb) {
    __shared__ float xT[FF * 128];
    __shared__ float wT[FF * 128];
    int m0 = blockIdx.x * 128;
    int tid = threadIdx.x;
    {
        int i = tid >> 1;
        int q0 = (tid & 1) * 4;
        bool ok = (m0 + i) < NNODES;
        const float4* xr = (const float4*)(x + (size_t)(m0 + i) * FF);
        const float4* wr = (const float4*)(W0 + (size_t)i * FF);
#pragma unroll
        for (int q = 0; q < 4; q++) {
            float4 v = ok ? xr[q0 + q] : make_float4(0.f, 0.f, 0.f, 0.f);
            int k = (q0 + q) * 4;
            xT[(k + 0) * 128 + i] = v.x; xT[(k + 1) * 128 + i] = v.y;
            xT[(k + 2) * 128 + i] = v.z; xT[(k + 3) * 128 + i] = v.w;
        }
#pragma unroll
        for (int q = 0; q < 4; q++) {
            float4 v = wr[q0 + q];
            int k = (q0 + q) * 4;
            wT[(k + 0) * 128 + i] = v.x; wT[(k + 1) * 128 + i] = v.y;
            wT[(k + 2) * 128 + i] = v.z; wT[(k + 3) * 128 + i] = v.w;
        }
    }
    __syncthreads();
    int tx = tid & 15, ty = tid >> 4;
    unsigned long long acc[8][4];
#pragma unroll
    for (int i = 0; i < 8; i++)
#pragma unroll
        for (int j = 0; j < 4; j++) acc[i][j] = 0ull;

    const float* aBase = xT + ty * 8;
    const float* bBase = wT + tx * 8;
#pragma unroll 4
    for (int k = 0; k < FF; k++) {
        float4 a0 = *(const float4*)(aBase + k * 128);
        float4 a1 = *(const float4*)(aBase + k * 128 + 4);
        const unsigned long long* bp = (const unsigned long long*)(bBase + k * 128);
        unsigned long long b0 = bp[0], b1 = bp[1], b2 = bp[2], b3 = bp[3];
        float av[8] = {a0.x, a0.y, a0.z, a0.w, a1.x, a1.y, a1.z, a1.w};
#pragma unroll
        for (int i = 0; i < 8; i++) {
            unsigned long long a2 = pack_dup(av[i]);
            fma2(acc[i][0], a2, b0); fma2(acc[i][1], a2, b1);
            fma2(acc[i][2], a2, b2); fma2(acc[i][3], a2, b3);
        }
    }
#pragma unroll
    for (int i = 0; i < 8; i++) {
        int row = m0 + ty * 8 + i;
        if (row < NNODES) {
            float2 v0 = unpack2(acc[i][0]), v1 = unpack2(acc[i][1]);
            float2 v2 = unpack2(acc[i][2]), v3 = unpack2(acc[i][3]);
            float4 o0 = make_float4(sigf(v0.x), sigf(v0.y), sigf(v1.x), sigf(v1.y));
            float4 o1 = make_float4(sigf(v2.x), sigf(v2.y), sigf(v3.x), sigf(v3.y));
            size_t off = (size_t)row * HH + tx * 8;
            *(float4*)(g_h + off) = o0;     *(float4*)(g_h + off + 4) = o1;
            *(float4*)(out_emb + off) = o0; *(float4*)(out_emb + off + 4) = o1;
            uint2 hh0, ll0, hh1, ll1;
            split4(o0, hh0, ll0);
            split4(o1, hh1, ll1);
            *(uint4*)(g_xh + off) = make_uint4(hh0.x, hh0.y, hh1.x, hh1.y);
            *(uint4*)(g_xl + off) = make_uint4(ll0.x, ll0.y, ll1.x, ll1.y);
        }
    }
}

// ---------------- CSR aggregation -> pre-split bf16 planes (unroll 4) ----------------
__global__ void aggregate_kernel() {
    int w = (blockIdx.x * 256 + threadIdx.x) >> 5;
    if (w >= NNODES) return;
    int lane = threadIdx.x & 31;
    int e0 = g_off[w], e1 = g_off[w + 1];
    float4 a = make_float4(0.f, 0.f, 0.f, 0.f);
    int e = e0;
    for (; e + 4 <= e1; e += 4) {
        int s0 = __ldcs(g_csr_src + e),     s1 = __ldcs(g_csr_src + e + 1);
        int s2 = __ldcs(g_csr_src + e + 2), s3 = __ldcs(g_csr_src + e + 3);
        float4 v0 = __ldg((const float4*)(g_h + (size_t)s0 * HH) + lane);
        float4 v1 = __ldg((const float4*)(g_h + (size_t)s1 * HH) + lane);
        float4 v2 = __ldg((const float4*)(g_h + (size_t)s2 * HH) + lane);
        float4 v3 = __ldg((const float4*)(g_h + (size_t)s3 * HH) + lane);
        a.x += (v0.x + v1.x) + (v2.x + v3.x);
        a.y += (v0.y + v1.y) + (v2.y + v3.y);
        a.z += (v0.z + v1.z) + (v2.z + v3.z);
        a.w += (v0.w + v1.w) + (v2.w + v3.w);
    }
    for (; e < e1; e++) {
        int s0 = __ldcs(g_csr_src + e);
        float4 v0 = __ldg((const float4*)(g_h + (size_t)s0 * HH) + lane);
        a.x += v0.x; a.y += v0.y; a.z += v0.z; a.w += v0.w;
    }
    uint2 hv, lv;
    split4(a, hv, lv);
    *((uint2*)(g_ah + (size_t)w * HH) + lane) = hv;
    *((uint2*)(g_al + (size_t)w * HH) + lane) = lv;
}

// ---------------- tensor-core GEMM tile (bf16 split-3), 128x128, K=KCH*64 ----------------
#define SAW2 72
#define MMA_SMEM (4 * 128 * SAW2 * 2)

// Main-loop only: leaves results in acc[4][4][4]; caller does the epilogue.
template <int KCH>
__device__ __forceinline__ void gemm_core(const unsigned short* __restrict__ A0h,
                                          const unsigned short* __restrict__ A0l,
                                          const unsigned short* __restrict__ A1h,
                                          const unsigned short* __restrict__ A1l,
                                          const unsigned short* __restrict__ Bh,
                                          const unsigned short* __restrict__ Bl,
                                          int j0, float acc[4][4][4]) {
    extern __shared__ unsigned short smx[];
    const int tid = threadIdx.x;
    const int m0 = blockIdx.x * 128;
    const int lane = tid & 31, wid = tid >> 5;
    const int wm = wid >> 2, wn = wid & 3;

    uint32_t sbase = (uint32_t)__cvta_generic_to_shared(smx);
    const uint32_t oAh = 0;
    const uint32_t oAl = 128 * SAW2 * 2;
    const uint32_t oBh = 2 * 128 * SAW2 * 2;
    const uint32_t oBl = 3 * 128 * SAW2 * 2;
    unsigned short* sAh = smx;
    unsigned short* sAl = smx + 128 * SAW2;
    unsigned short* sBh = smx + 2 * 128 * SAW2;
    unsigned short* sBl = smx + 3 * 128 * SAW2;

    const int ai = tid >> 1;
    const int half = tid & 1;
    const size_t aoff = (size_t)(m0 + ai) * HH;
    const size_t boff = (size_t)(j0 + ai) * (KCH * 64);
    const uint4* a0h = (const uint4*)(A0h + aoff);
    const uint4* a0l = (const uint4*)(A0l + aoff);
    const uint4* a1h = (const uint4*)(A1h + aoff);
    const uint4* a1l = (const uint4*)(A1l + aoff);
    const uint4* brh = (const uint4*)(Bh + boff);
    const uint4* brl = (const uint4*)(Bl + boff);

#pragma unroll
    for (int ch = 0; ch < KCH; ch++) {
        const uint4* sh = (KCH == 2 || ch < 2) ? a0h : a1h;
        const uint4* sl = (KCH == 2 || ch < 2) ? a0l : a1l;
        const int ach = ch & 1;
        uint4* dAh = (uint4*)(sAh + ai * SAW2 + half * 32);
        uint4* dAl = (uint4*)(sAl + ai * SAW2 + half * 32);
        uint4* dBh = (uint4*)(sBh + ai * SAW2 + half * 32);
        uint4* dBl = (uint4*)(sBl + ai * SAW2 + half * 32);
#pragma unroll
        for (int q = 0; q < 4; q++) {
            dAh[q] = sh[ach * 8 + half * 4 + q];
            dAl[q] = sl[ach * 8 + half * 4 + q];
            dBh[q] = brh[ch * 8 + half * 4 + q];
            dBl[q] = brl[ch * 8 + half * 4 + q];
        }
        __syncthreads();

#pragma unroll
        for (int ks = 0; ks < 4; ks++) {
            unsigned bh[2][4], bl[2][4];
#pragma unroll
            for (int np = 0; np < 2; np++) {
                uint32_t off = ((wn * 32 + np * 16 + (lane & 15)) * SAW2 +
                                ks * 16 + (lane >> 4) * 8) * 2;
                ldm4(bh[np], sbase + oBh + off);
                ldm4(bl[np], sbase + oBl + off);
            }
#pragma unroll
            for (int mt = 0; mt < 4; mt++) {
                unsigned a_h[4], a_l[4];
                uint32_t off = ((wm * 64 + mt * 16 + (lane & 15)) * SAW2 +
                                ks * 16 + (lane >> 4) * 8) * 2;
                ldm4(a_h, sbase + oAh + off);
                ldm4(a_l, sbase + oAl + off);
#pragma unroll
                for (int nt = 0; nt < 4; nt++) {
                    int np = nt >> 1, od = nt & 1;
                    float* c = acc[mt][nt];
                    mma16816(c, a_h, bh[np][od], bh[np][2 + od]);
                    mma16816(c, a_h, bl[np][od], bl[np][2 + od]);
                    mma16816(c, a_l, bh[np][od], bh[np][2 + od]);
                }
            }
        }
        __syncthreads();
    }
}

// launch A: y<2 -> rz K=256 tiles; y==2 -> h_n GEMM
__global__ __launch_bounds__(256, 2)
void mma_gemm_a(const unsigned short* __restrict__ rzh,
                const unsigned short* __restrict__ rzl, int M) {
    float acc[4][4][4];
#pragma unroll
    for (int a = 0; a < 4; a++)
#pragma unroll
        for (int b = 0; b < 4; b++)
#pragma unroll
            for (int c = 0; c < 4; c++) acc[a][b][c] = 0.f;

    float* C;
    int ldc, j0;
    if (blockIdx.y < 2) {
        j0 = blockIdx.y * 128;
        gemm_core<4>(g_ah, g_al, g_xh, g_xl, rzh, rzl, j0, acc);
        C = g_grz; ldc = 256;
    } else {
        j0 = 0;
        gemm_core<2>(g_xh, g_xl, g_xh, g_xl, g_hn_h, g_hn_l, 0, acc);
        C = g_ghn; ldc = HH;
    }
    const int tid = threadIdx.x;
    const int m0 = blockIdx.x * 128;
    const int lane = tid & 31, wid = tid >> 5;
    const int wm = wid >> 2, wn = wid & 3;
#pragma unroll
    for (int mt = 0; mt < 4; mt++) {
        int r0 = m0 + wm * 64 + mt * 16 + (lane >> 2);
#pragma unroll
        for (int nt = 0; nt < 4; nt++) {
            int col = j0 + wn * 32 + nt * 8 + (lane & 3) * 2;
            if (r0 < M)
                __stcs((float2*)(C + (size_t)r0 * ldc + col),
                       make_float2(acc[mt][nt][0], acc[mt][nt][1]));
            if (r0 + 8 < M)
                __stcs((float2*)(C + (size_t)(r0 + 8) * ldc + col),
                       make_float2(acc[mt][nt][2], acc[mt][nt][3]));
        }
    }
}

// launch B: i_n GEMM (agg @ W_comb_n) + fused GRU epilogue.
// i_n stays in registers; reads grz/ghn/h for the block's rows, writes h (+planes).
__global__ __launch_bounds__(256, 2)
void gin_gru_kernel(const unsigned short* __restrict__ cnh,
                    const unsigned short* __restrict__ cnl,
                    const float* __restrict__ b_ih, const float* __restrict__ b_hh,
                    int write_planes, int M) {
    float acc[4][4][4];
#pragma unroll
    for (int a = 0; a < 4; a++)
#pragma unroll
        for (int b = 0; b < 4; b++)
#pragma unroll
            for (int c = 0; c < 4; c++) acc[a][b][c] = 0.f;

    gemm_core<2>(g_ah, g_al, g_ah, g_al, cnh, cnl, 0, acc);

    const int tid = threadIdx.x;
    const int m0 = blockIdx.x * 128;
    const int lane = tid & 31, wid = tid >> 5;
    const int wm = wid >> 2, wn = wid & 3;

#pragma unroll
    for (int nt = 0; nt < 4; nt++) {
        int col = wn * 32 + nt * 8 + (lane & 3) * 2;
        float2 bir = *(const float2*)(b_ih + col);
        float2 biz = *(const float2*)(b_ih + 128 + col);
        float2 bin = *(const float2*)(b_ih + 256 + col);
        float2 bhr = *(const float2*)(b_hh + col);
        float2 bhz = *(const float2*)(b_hh + 128 + col);
        float2 bhn = *(const float2*)(b_hh + 256 + col);
#pragma unroll
        for (int mt = 0; mt < 4; mt++) {
#pragma unroll
            for (int hf = 0; hf < 2; hf++) {
                int row = m0 + wm * 64 + mt * 16 + (lane >> 2) + hf * 8;
                if (row >= M) continue;
                float i0 = acc[mt][nt][hf * 2];
                float i1 = acc[mt][nt][hf * 2 + 1];
                size_t rz = (size_t)row * 256 + col;
                float2 rr = __ldcs((const float2*)(g_grz + rz));
                float2 zz = __ldcs((const float2*)(g_grz + rz + 128));
                float2 hn = __ldcs((const float2*)(g_ghn + (size_t)row * HH + col));
                float2 hv = *(const float2*)(g_h + (size_t)row * HH + col);
                float r0v = sigf(rr.x + bir.x + bhr.x);
                float r1v = sigf(rr.y + bir.y + bhr.y);
                float z0v = sigf(zz.x + biz.x + bhz.x);
                float z1v = sigf(zz.y + biz.y + bhz.y);
                float n0v = tanhfast(i0 + bin.x + r0v * (hn.x + bhn.x));
                float n1v = tanhfast(i1 + bin.y + r1v * (hn.y + bhn.y));
                float o0 = (1.f - z0v) * n0v + z0v * hv.x;
                float o1 = (1.f - z1v) * n1v + z1v * hv.y;
                *(float2*)(g_h + (size_t)row * HH + col) = make_float2(o0, o1);
                if (write_planes) {
                    unsigned hh, ll;
                    split2(o0, o1, hh, ll);
                    *(unsigned*)(g_xh + (size_t)row * HH + col) = hh;
                    *(unsigned*)(g_xl + (size_t)row * HH + col) = ll;
                }
            }
        }
    }
}

// ---------------- head + per-graph sums (after last layer) ----------------
__global__ void lin_kernel(const float* __restrict__ lw, const float* __restrict__ lb,
                           float* __restrict__ out_unc) {
    int gw = (blockIdx.x * 256 + threadIdx.x) >> 5;
    int lane = threadIdx.x & 31;
    float4 a = *(const float4*)(g_h + (size_t)gw * HH + lane * 4);
    a.x = fmaxf(a.x, 0.f); a.y = fmaxf(a.y, 0.f);
    a.z = fmaxf(a.z, 0.f); a.w = fmaxf(a.w, 0.f);
    float4 w = __ldg((const float4*)lw + lane);
    float s = a.x * w.x + a.y * w.y + a.z * w.z + a.w * w.w;
#pragma unroll
    for (int o = 16; o; o >>= 1) s += __shfl_xor_sync(0xffffffffu, s, o);
    if (lane == 0) {
        float v = s + __ldg(lb);
        g_outv[gw] = v;
        out_unc[gw] = v;
        int b = g_batch[gw];
        atomicAdd(&g_gsum[b], v);
        atomicAdd(&g_gcnt[b], 1.f);
    }
}

__global__ void correct_kernel(float* __restrict__ out_corr) {
    int n = blockIdx.x * 256 + threadIdx.x;
    if (n >= NNODES) return;
    int b = g_batch[n];
    out_corr[n] = g_outv[n] - g_gsum[b] / fmaxf(g_gcnt[b], 1.f);
}

// ---------------- launcher ----------------
extern "C" void kernel_launch(void* const* d_in, const int* in_sizes, int n_in,
                              void* d_out, int out_size) {
    const float* x = (const float*)d_in[0];
    const void* edge = d_in[1];
    const void* batch = d_in[2];
    int wi = 3;
    if (in_sizes[3] == 1) wi = 4;
    const float* W0     = (const float*)d_in[wi + 0];
    const float* conv_w = (const float*)d_in[wi + 1];
    const float* w_ih   = (const float*)d_in[wi + 2];
    const float* b_ih   = (const float*)d_in[wi + 3];
    const float* w_hh   = (const float*)d_in[wi + 4];
    const float* b_hh   = (const float*)d_in[wi + 5];
    const float* lin1_w = (const float*)d_in[wi + 6];
    const float* lin1_b = (const float*)d_in[wi + 7];

    float* out = (float*)d_out;
    float* out_corr = out;
    float* out_emb  = out + NNODES;
    float* out_unc  = out + NNODES + (size_t)NNODES * HH;

    cudaFuncSetAttribute(mma_gemm_a, cudaFuncAttributeMaxDynamicSharedMemorySize,
                         MMA_SMEM);
    cudaFuncSetAttribute(gin_gru_kernel, cudaFuncAttributeMaxDynamicSharedMemorySize,
                         MMA_SMEM);
    cudaFuncSetAttribute(fold_gemm_kernel, cudaFuncAttributeMaxDynamicSharedMemorySize,
                         FOLD_SMEM);

    unsigned short *p_rzh, *p_rzl, *p_cnh, *p_cnl;
    cudaGetSymbolAddress((void**)&p_rzh, g_rz_h);
    cudaGetSymbolAddress((void**)&p_rzl, g_rz_l);
    cudaGetSymbolAddress((void**)&p_cnh, g_cn_h);
    cudaGetSymbolAddress((void**)&p_cnl, g_cn_l);

    // setup
    zero_init_kernel<<<(NNODES + 255) / 256, 256>>>();
    detect_kernel<<<dim3(256, 2), 256>>>((const unsigned int*)edge,
                                         (const unsigned int*)batch);
    convert_edges_kernel<<<(EEDGES + 255) / 256, 256>>>(edge);
    convert_batch_kernel<<<(NNODES + 255) / 256, 256>>>(batch);
    scan1_kernel<<<NSCAN, SCANB>>>();
    scan2_kernel<<<1, 256>>>();
    scan3_kernel<<<NSCAN, SCANB>>>();
    fill_csr_kernel<<<(EEDGES + 255) / 256, 256>>>();
    fold_gemm_kernel<<<dim3(3, 1, LLAYERS), 256, FOLD_SMEM>>>(w_ih, conv_w);
    whh_split_kernel<<<(H3 * HH + 255) / 256, 256>>>(w_hh);

    const int MT = (NNODES + 127) / 128;   // 782
    embed_kernel<<<MT, 256>>>(x, W0, out_emb);

    for (int l = 0; l < LLAYERS; l++) {
        int last = (l == LLAYERS - 1);
        aggregate_kernel<<<NNODES * 32 / 256, 256>>>();
        mma_gemm_a<<<dim3(MT, 3), 256, MMA_SMEM>>>(
            p_rzh + (size_t)l * 256 * 256, p_rzl + (size_t)l * 256 * 256, NNODES);
        gin_gru_kernel<<<MT, 256, MMA_SMEM>>>(
            p_cnh + (size_t)l * HH * HH, p_cnl + (size_t)l * HH * HH,
            b_ih, b_hh, !last, NNODES);
    }

    lin_kernel<<<NNODES * 32 / 256, 256>>>(lin1_w, lin1_b, out_unc);
    correct_kernel<<<(NNODES + 255) / 256, 256>>>(out_corr);
}

// round 16
// speedup vs baseline: 1.2666x; 1.2666x over previous
#include <cuda_runtime.h>
#include <cuda_bf16.h>
#include <cstdint>

#define NNODES 100000
#define NPAD 100096                     // padded rows (multiple of 128)
#define EEDGES 1600000
#define FF 32
#define HH 128
#define LLAYERS 4
#define GG 64
#define H3 384
#define SCANB 512
#define NSCAN ((NNODES + SCANB - 1) / SCANB)   // 196

// ---------------- scratch (device globals; no allocation) ----------------
__device__ float g_h[(size_t)NNODES * HH];
__device__ float g_grz[(size_t)NNODES * 256];   // combined r,z pre-activations (gi+gh)
__device__ float g_gin[(size_t)NNODES * HH];    // i_n
__device__ float g_ghn[(size_t)NNODES * HH];    // h_n
__device__ float g_outv[NNODES];
__device__ float g_gsum[GG];
__device__ float g_gcnt[GG];
__device__ int   g_src[EEDGES];
__device__ int   g_dst[EEDGES];
__device__ int   g_batch[NNODES];
__device__ int   g_edge_i32;
__device__ int   g_batch_i32;
// CSR
__device__ int   g_deg[NNODES];
__device__ int   g_cur[NNODES];
__device__ int   g_off[NNODES + 1];
__device__ int   g_part[NSCAN];
__device__ int   g_part2[NSCAN];
__device__ int   g_csr_src[EEDGES];

// pre-split bf16 A operands (hi/lo planes), padded rows
__device__ unsigned short g_ah[(size_t)NPAD * HH];   // agg hi
__device__ unsigned short g_al[(size_t)NPAD * HH];   // agg lo
__device__ unsigned short g_xh[(size_t)NPAD * HH];   // h hi
__device__ unsigned short g_xl[(size_t)NPAD * HH];   // h lo

// bf16 split weights (hi/lo), n-major:
// rz combined: [l][col 0..255][k 0..255]; k<128 -> W_comb_rz, k>=128 -> w_hh_rz
__device__ unsigned short g_rz_h[(size_t)LLAYERS * 256 * 256];
__device__ unsigned short g_rz_l[(size_t)LLAYERS * 256 * 256];
// n gates: i_n weights [l][128][128], h_n weights [128][128]
__device__ unsigned short g_cn_h[(size_t)LLAYERS * HH * HH];
__device__ unsigned short g_cn_l[(size_t)LLAYERS * HH * HH];
__device__ unsigned short g_hn_h[HH * HH];
__device__ unsigned short g_hn_l[HH * HH];

// ---------------- math helpers ----------------
__device__ __forceinline__ float sigf(float x) { return 1.f / (1.f + __expf(-x)); }
__device__ __forceinline__ float tanhfast(float x) {
    float ax = fabsf(x);
    float e = __expf(-2.f * ax);
    float t = (1.f - e) / (1.f + e);
    return copysignf(t, x);
}
__device__ __forceinline__ void fma2(unsigned long long& d, unsigned long long a,
                                     unsigned long long b) {
    asm("fma.rn.f32x2 %0, %1, %2, %3;" : "=l"(d) : "l"(a), "l"(b), "l"(d));
}
__device__ __forceinline__ unsigned long long pack_dup(float x) {
    unsigned long long r;
    asm("mov.b64 %0, {%1, %1};" : "=l"(r) : "f"(x));
    return r;
}
__device__ __forceinline__ float2 unpack2(unsigned long long v) {
    float2 r;
    asm("mov.b64 {%0, %1}, %2;" : "=f"(r.x), "=f"(r.y) : "l"(v));
    return r;
}
__device__ __forceinline__ void split1(float a, unsigned short& h, unsigned short& l) {
    __nv_bfloat16 ha = __float2bfloat16_rn(a);
    float ra = a - __bfloat162float(ha);
    __nv_bfloat16 la = __float2bfloat16_rn(ra);
    h = __bfloat16_as_ushort(ha);
    l = __bfloat16_as_ushort(la);
}
__device__ __forceinline__ void split2(float a, float b, unsigned& h, unsigned& l) {
    unsigned short ha, la, hb, lb;
    split1(a, ha, la);
    split1(b, hb, lb);
    h = (unsigned)ha | ((unsigned)hb << 16);
    l = (unsigned)la | ((unsigned)lb << 16);
}
__device__ __forceinline__ void split4(float4 v, uint2& h, uint2& l) {
    split2(v.x, v.y, h.x, l.x);
    split2(v.z, v.w, h.y, l.y);
}
__device__ __forceinline__ void ldm4(unsigned r[4], uint32_t addr) {
    asm volatile("ldmatrix.sync.aligned.m8n8.x4.shared.b16 {%0,%1,%2,%3}, [%4];\n"
                 : "=r"(r[0]), "=r"(r[1]), "=r"(r[2]), "=r"(r[3])
                 : "r"(addr));
}
__device__ __forceinline__ void mma16816(float* c, const unsigned a[4],
                                         unsigned b0, unsigned b1) {
    asm("mma.sync.aligned.m16n8k16.row.col.f32.bf16.bf16.f32 "
        "{%0,%1,%2,%3}, {%4,%5,%6,%7}, {%8,%9}, {%0,%1,%2,%3};\n"
        : "+f"(c[0]), "+f"(c[1]), "+f"(c[2]), "+f"(c[3])
        : "r"(a[0]), "r"(a[1]), "r"(a[2]), "r"(a[3]), "r"(b0), "r"(b1));
}

// ---------------- setup kernels ----------------
__global__ void zero_init_kernel() {
    int i = blockIdx.x * 256 + threadIdx.x;
    if (i < NNODES) { g_deg[i] = 0; g_cur[i] = 0; }
    if (i < GG) { g_gsum[i] = 0.f; g_gcnt[i] = 0.f; }
    if (i == 0) { g_edge_i32 = 0; g_batch_i32 = 0; }
}
__global__ void detect_kernel(const unsigned int* __restrict__ pe,
                              const unsigned int* __restrict__ pb) {
    int which = blockIdx.y;
    const unsigned int* p = which ? pb : pe;
    long long nwords = which ? (long long)NNODES : 2LL * EEDGES;
    long long i = 1 + 2LL * (blockIdx.x * (long long)blockDim.x + threadIdx.x);
    long long stride = 2LL * gridDim.x * blockDim.x;
    int found = 0;
    for (; i < nwords; i += stride)
        if (p[i]) { found = 1; break; }
    if (found) { if (which == 0) g_edge_i32 = 1; else g_batch_i32 = 1; }
}
__global__ void convert_edges_kernel(const void* __restrict__ e) {
    int i = blockIdx.x * 256 + threadIdx.x;
    if (i >= EEDGES) return;
    int s, d;
    if (g_edge_i32) {
        const int* p = (const int*)e;
        s = __ldcs(p + i); d = __ldcs(p + EEDGES + i);
    } else {
        const long long* p = (const long long*)e;
        s = (int)__ldcs(p + i); d = (int)__ldcs(p + EEDGES + i);
    }
    g_src[i] = s;
    g_dst[i] = d;
    atomicAdd(&g_deg[d], 1);
}
__global__ void convert_batch_kernel(const void* __restrict__ b) {
    int i = blockIdx.x * 256 + threadIdx.x;
    if (i >= NNODES) return;
    if (g_batch_i32) g_batch[i] = ((const int*)b)[i];
    else             g_batch[i] = (int)((const long long*)b)[i];
}

// ---------------- scan (exclusive prefix over degrees) ----------------
__global__ void scan1_kernel() {
    __shared__ int s[SCANB];
    int t = threadIdx.x;
    int i = blockIdx.x * SCANB + t;
    int v = (i < NNODES) ? g_deg[i] : 0;
    s[t] = v;
    __syncthreads();
#pragma unroll
    for (int o = 1; o < SCANB; o <<= 1) {
        int x = (t >= o) ? s[t - o] : 0;
        __syncthreads();
        s[t] += x;
        __syncthreads();
    }
    if (i < NNODES) g_off[i] = s[t] - v;
    if (t == SCANB - 1) g_part[blockIdx.x] = s[t];
}
__global__ void scan2_kernel() {
    __shared__ int s[256];
    int t = threadIdx.x;
    int v = (t < NSCAN) ? g_part[t] : 0;
    s[t] = v;
    __syncthreads();
#pragma unroll
    for (int o = 1; o < 256; o <<= 1) {
        int x = (t >= o) ? s[t - o] : 0;
        __syncthreads();
        s[t] += x;
        __syncthreads();
    }
    if (t < NSCAN) g_part2[t] = s[t] - v;
}
__global__ void scan3_kernel() {
    int i = blockIdx.x * SCANB + threadIdx.x;
    if (i < NNODES) g_off[i] += g_part2[blockIdx.x];
    if (i == 0) g_off[NNODES] = EEDGES;
}
__global__ void fill_csr_kernel() {
    int i = blockIdx.x * 256 + threadIdx.x;
    if (i >= EEDGES) return;
    int d = g_dst[i];
    int p = atomicAdd(&g_cur[d], 1);
    g_csr_src[g_off[d] + p] = g_src[i];
}

// ---------------- fold GEMM: W_comb = w_ih x conv_w; epilogue splits + routes ----------------
#define FOLD_SMEM (2 * 128 * 128 * 4)
__global__ void fold_gemm_kernel(const float* __restrict__ A,
                                 const float* __restrict__ Bbase) {
    const float* B = Bbase + (size_t)blockIdx.z * HH * HH;
    const int l = blockIdx.z;
    extern __shared__ float smf[];
    float* aT = smf;
    float* ws = smf + 128 * 128;
    int m0 = blockIdx.x * 128;
    int tid = threadIdx.x;
    {
        int i = tid >> 1;
        int kq0 = (tid & 1) * 16;
        const float4* Ar = (const float4*)(A + (size_t)(m0 + i) * 128);
#pragma unroll
        for (int q = 0; q < 16; q++) {
            int k4 = kq0 + q;
            float4 v = Ar[k4];
            aT[(k4 * 4 + 0) * 128 + i] = v.x; aT[(k4 * 4 + 1) * 128 + i] = v.y;
            aT[(k4 * 4 + 2) * 128 + i] = v.z; aT[(k4 * 4 + 3) * 128 + i] = v.w;
        }
    }
    {
        int k = tid >> 1;
        int kq0 = (tid & 1) * 16;
        const float4* Br = (const float4*)(B + (size_t)k * 128);
#pragma unroll
        for (int q = 0; q < 16; q++) {
            int k4 = kq0 + q;
            float4 v = Br[k4];
            ws[(k4 * 4 + 0) * 128 + k] = v.x; ws[(k4 * 4 + 1) * 128 + k] = v.y;
            ws[(k4 * 4 + 2) * 128 + k] = v.z; ws[(k4 * 4 + 3) * 128 + k] = v.w;
        }
    }
    __syncthreads();

    int tx = tid & 15, ty = tid >> 4;
    unsigned long long acc[8][4];
#pragma unroll
    for (int i = 0; i < 8; i++)
#pragma unroll
        for (int j = 0; j < 4; j++) acc[i][j] = 0ull;

    const float* aBase = aT + ty * 8;
    const float* bBase = ws + tx * 8;
#pragma unroll 4
    for (int k = 0; k < 128; k++) {
        float4 a0 = *(const float4*)(aBase + k * 128);
        float4 a1 = *(const float4*)(aBase + k * 128 + 4);
        const unsigned long long* bp = (const unsigned long long*)(bBase + k * 128);
        unsigned long long b0 = bp[0], b1 = bp[1], b2 = bp[2], b3 = bp[3];
        float av[8] = {a0.x, a0.y, a0.z, a0.w, a1.x, a1.y, a1.z, a1.w};
#pragma unroll
        for (int i = 0; i < 8; i++) {
            unsigned long long a2 = pack_dup(av[i]);
            fma2(acc[i][0], a2, b0); fma2(acc[i][1], a2, b1);
            fma2(acc[i][2], a2, b2); fma2(acc[i][3], a2, b3);
        }
    }
#pragma unroll
    for (int i = 0; i < 8; i++) {
        int row = m0 + ty * 8 + i;          // gate-output index 0..383
        float vv[8];
        float2 v0 = unpack2(acc[i][0]), v1 = unpack2(acc[i][1]);
        float2 v2 = unpack2(acc[i][2]), v3 = unpack2(acc[i][3]);
        vv[0] = v0.x; vv[1] = v0.y; vv[2] = v1.x; vv[3] = v1.y;
        vv[4] = v2.x; vv[5] = v2.y; vv[6] = v3.x; vv[7] = v3.y;
        unsigned short hs[8], ls[8];
#pragma unroll
        for (int q = 0; q < 8; q++) split1(vv[q], hs[q], ls[q]);
        if (row < 256) {                    // r,z gates -> rz combined, k slot [0,128)
            size_t off = ((size_t)l * 256 + row) * 256 + tx * 8;
#pragma unroll
            for (int q = 0; q < 8; q++) { g_rz_h[off + q] = hs[q]; g_rz_l[off + q] = ls[q]; }
        } else {                            // n gate -> cn
            size_t off = ((size_t)l * HH + (row - 256)) * HH + tx * 8;
#pragma unroll
            for (int q = 0; q < 8; q++) { g_cn_h[off + q] = hs[q]; g_cn_l[off + q] = ls[q]; }
        }
    }
}

__global__ void whh_split_kernel(const float* __restrict__ whh) {
    int idx = blockIdx.x * 256 + threadIdx.x;
    if (idx >= H3 * HH) return;
    int o = idx >> 7;
    int k = idx & 127;
    unsigned short h, lo;
    split1(whh[idx], h, lo);
    if (o < 256) {                          // r,z -> rz combined, k slot [128,256), all layers
#pragma unroll
        for (int l = 0; l < LLAYERS; l++) {
            size_t off = ((size_t)l * 256 + o) * 256 + 128 + k;
            g_rz_h[off] = h; g_rz_l[off] = lo;
        }
    } else {                                // n -> hn
        size_t off = (size_t)(o - 256) * HH + k;
        g_hn_h[off] = h; g_hn_l[off] = lo;
    }
}

// ---------------- embed: h = sigmoid(x @ W0^T); writes h fp32 + planes ----------------
__global__ void embed_kernel(const float* __restrict__ x, const float* __restrict__ W0,
                             float* __restrict__ out_emb) {
    __shared__ float xT[FF * 128];
    __shared__ float wT[FF * 128];
    int m0 = blockIdx.x * 128;
    int tid = threadIdx.x;
    {
        int i = tid >> 1;
        int q0 = (tid & 1) * 4;
        bool ok = (m0 + i) < NNODES;
        const float4* xr = (const float4*)(x + (size_t)(m0 + i) * FF);
        const float4* wr = (const float4*)(W0 + (size_t)i * FF);
#pragma unroll
        for (int q = 0; q < 4; q++) {
            float4 v = ok ? xr[q0 + q] : make_float4(0.f, 0.f, 0.f, 0.f);
            int k = (q0 + q) * 4;
            xT[(k + 0) * 128 + i] = v.x; xT[(k + 1) * 128 + i] = v.y;
            xT[(k + 2) * 128 + i] = v.z; xT[(k + 3) * 128 + i] = v.w;
        }
#pragma unroll
        for (int q = 0; q < 4; q++) {
            float4 v = wr[q0 + q];
            int k = (q0 + q) * 4;
            wT[(k + 0) * 128 + i] = v.x; wT[(k + 1) * 128 + i] = v.y;
            wT[(k + 2) * 128 + i] = v.z; wT[(k + 3) * 128 + i] = v.w;
        }
    }
    __syncthreads();
    int tx = tid & 15, ty = tid >> 4;
    unsigned long long acc[8][4];
#pragma unroll
    for (int i = 0; i < 8; i++)
#pragma unroll
        for (int j = 0; j < 4; j++) acc[i][j] = 0ull;

    const float* aBase = xT + ty * 8;
    const float* bBase = wT + tx * 8;
#pragma unroll 4
    for (int k = 0; k < FF; k++) {
        float4 a0 = *(const float4*)(aBase + k * 128);
        float4 a1 = *(const float4*)(aBase + k * 128 + 4);
        const unsigned long long* bp = (const unsigned long long*)(bBase + k * 128);
        unsigned long long b0 = bp[0], b1 = bp[1], b2 = bp[2], b3 = bp[3];
        float av[8] = {a0.x, a0.y, a0.z, a0.w, a1.x, a1.y, a1.z, a1.w};
#pragma unroll
        for (int i = 0; i < 8; i++) {
            unsigned long long a2 = pack_dup(av[i]);
            fma2(acc[i][0], a2, b0); fma2(acc[i][1], a2, b1);
            fma2(acc[i][2], a2, b2); fma2(acc[i][3], a2, b3);
        }
    }
#pragma unroll
    for (int i = 0; i < 8; i++) {
        int row = m0 + ty * 8 + i;
        if (row < NNODES) {
            float2 v0 = unpack2(acc[i][0]), v1 = unpack2(acc[i][1]);
            float2 v2 = unpack2(acc[i][2]), v3 = unpack2(acc[i][3]);
            float4 o0 = make_float4(sigf(v0.x), sigf(v0.y), sigf(v1.x), sigf(v1.y));
            float4 o1 = make_float4(sigf(v2.x), sigf(v2.y), sigf(v3.x), sigf(v3.y));
            size_t off = (size_t)row * HH + tx * 8;
            *(float4*)(g_h + off) = o0;     *(float4*)(g_h + off + 4) = o1;
            *(float4*)(out_emb + off) = o0; *(float4*)(out_emb + off + 4) = o1;
            uint2 hh0, ll0, hh1, ll1;
            split4(o0, hh0, ll0);
            split4(o1, hh1, ll1);
            *(uint4*)(g_xh + off) = make_uint4(hh0.x, hh0.y, hh1.x, hh1.y);
            *(uint4*)(g_xl + off) = make_uint4(ll0.x, ll0.y, ll1.x, ll1.y);
        }
    }
}

// ---------------- CSR aggregation -> pre-split bf16 planes (unroll 4) ----------------
__global__ void aggregate_kernel() {
    int w = (blockIdx.x * 256 + threadIdx.x) >> 5;
    if (w >= NNODES) return;
    int lane = threadIdx.x & 31;
    int e0 = g_off[w], e1 = g_off[w + 1];
    float4 a = make_float4(0.f, 0.f, 0.f, 0.f);
    int e = e0;
    for (; e + 4 <= e1; e += 4) {
        int s0 = __ldcs(g_csr_src + e),     s1 = __ldcs(g_csr_src + e + 1);
        int s2 = __ldcs(g_csr_src + e + 2), s3 = __ldcs(g_csr_src + e + 3);
        float4 v0 = __ldg((const float4*)(g_h + (size_t)s0 * HH) + lane);
        float4 v1 = __ldg((const float4*)(g_h + (size_t)s1 * HH) + lane);
        float4 v2 = __ldg((const float4*)(g_h + (size_t)s2 * HH) + lane);
        float4 v3 = __ldg((const float4*)(g_h + (size_t)s3 * HH) + lane);
        a.x += (v0.x + v1.x) + (v2.x + v3.x);
        a.y += (v0.y + v1.y) + (v2.y + v3.y);
        a.z += (v0.z + v1.z) + (v2.z + v3.z);
        a.w += (v0.w + v1.w) + (v2.w + v3.w);
    }
    for (; e < e1; e++) {
        int s0 = __ldcs(g_csr_src + e);
        float4 v0 = __ldg((const float4*)(g_h + (size_t)s0 * HH) + lane);
        a.x += v0.x; a.y += v0.y; a.z += v0.z; a.w += v0.w;
    }
    uint2 hv, lv;
    split4(a, hv, lv);
    *((uint2*)(g_ah + (size_t)w * HH) + lane) = hv;
    *((uint2*)(g_al + (size_t)w * HH) + lane) = lv;
}

// ---------------- tensor-core GEMM tile (bf16 split-3), 128x128, K=KCH*64 ----------------
// KCH=4: chunks 0-1 read A0 planes, 2-3 read A1 planes (concatenated-K rz GEMM).
// KCH=2: A1 unused (plain K=128).
#define SAW2 72
#define MMA_SMEM (4 * 128 * SAW2 * 2)

template <int KCH>
__device__ __forceinline__ void gemm_tile(const unsigned short* __restrict__ A0h,
                                          const unsigned short* __restrict__ A0l,
                                          const unsigned short* __restrict__ A1h,
                                          const unsigned short* __restrict__ A1l,
                                          const unsigned short* __restrict__ Bh,
                                          const unsigned short* __restrict__ Bl,
                                          float* __restrict__ C, int M, int ldc, int j0) {
    extern __shared__ unsigned short smx[];
    const int tid = threadIdx.x;
    const int m0 = blockIdx.x * 128;
    const int lane = tid & 31, wid = tid >> 5;
    const int wm = wid >> 2, wn = wid & 3;

    float acc[4][4][4];
#pragma unroll
    for (int a = 0; a < 4; a++)
#pragma unroll
        for (int b = 0; b < 4; b++)
#pragma unroll
            for (int c = 0; c < 4; c++) acc[a][b][c] = 0.f;

    uint32_t sbase = (uint32_t)__cvta_generic_to_shared(smx);
    const uint32_t oAh = 0;
    const uint32_t oAl = 128 * SAW2 * 2;
    const uint32_t oBh = 2 * 128 * SAW2 * 2;
    const uint32_t oBl = 3 * 128 * SAW2 * 2;
    unsigned short* sAh = smx;
    unsigned short* sAl = smx + 128 * SAW2;
    unsigned short* sBh = smx + 2 * 128 * SAW2;
    unsigned short* sBl = smx + 3 * 128 * SAW2;

    const int ai = tid >> 1;
    const int half = tid & 1;
    const size_t aoff = (size_t)(m0 + ai) * HH;
    const size_t boff = (size_t)(j0 + ai) * (KCH * 64);
    const uint4* a0h = (const uint4*)(A0h + aoff);
    const uint4* a0l = (const uint4*)(A0l + aoff);
    const uint4* a1h = (const uint4*)(A1h + aoff);
    const uint4* a1l = (const uint4*)(A1l + aoff);
    const uint4* brh = (const uint4*)(Bh + boff);
    const uint4* brl = (const uint4*)(Bl + boff);

#pragma unroll
    for (int ch = 0; ch < KCH; ch++) {
        const uint4* sh = (KCH == 2 || ch < 2) ? a0h : a1h;
        const uint4* sl = (KCH == 2 || ch < 2) ? a0l : a1l;
        const int ach = ch & 1;
        uint4* dAh = (uint4*)(sAh + ai * SAW2 + half * 32);
        uint4* dAl = (uint4*)(sAl + ai * SAW2 + half * 32);
        uint4* dBh = (uint4*)(sBh + ai * SAW2 + half * 32);
        uint4* dBl = (uint4*)(sBl + ai * SAW2 + half * 32);
#pragma unroll
        for (int q = 0; q < 4; q++) {
            dAh[q] = sh[ach * 8 + half * 4 + q];
            dAl[q] = sl[ach * 8 + half * 4 + q];
            dBh[q] = brh[ch * 8 + half * 4 + q];
            dBl[q] = brl[ch * 8 + half * 4 + q];
        }
        __syncthreads();

#pragma unroll
        for (int ks = 0; ks < 4; ks++) {
            unsigned bh[2][4], bl[2][4];
#pragma unroll
            for (int np = 0; np < 2; np++) {
                uint32_t off = ((wn * 32 + np * 16 + (lane & 15)) * SAW2 +
                                ks * 16 + (lane >> 4) * 8) * 2;
                ldm4(bh[np], sbase + oBh + off);
                ldm4(bl[np], sbase + oBl + off);
            }
#pragma unroll
            for (int mt = 0; mt < 4; mt++) {
                unsigned a_h[4], a_l[4];
                uint32_t off = ((wm * 64 + mt * 16 + (lane & 15)) * SAW2 +
                                ks * 16 + (lane >> 4) * 8) * 2;
                ldm4(a_h, sbase + oAh + off);
                ldm4(a_l, sbase + oAl + off);
#pragma unroll
                for (int nt = 0; nt < 4; nt++) {
                    int np = nt >> 1, od = nt & 1;
                    float* c = acc[mt][nt];
                    mma16816(c, a_h, bh[np][od], bh[np][2 + od]);
                    mma16816(c, a_h, bl[np][od], bl[np][2 + od]);
                    mma16816(c, a_l, bh[np][od], bh[np][2 + od]);
                }
            }
        }
        __syncthreads();
    }

    // streaming epilogue (gates read exactly once by gru)
#pragma unroll
    for (int mt = 0; mt < 4; mt++) {
        int r0 = m0 + wm * 64 + mt * 16 + (lane >> 2);
#pragma unroll
        for (int nt = 0; nt < 4; nt++) {
            int col = j0 + wn * 32 + nt * 8 + (lane & 3) * 2;
            if (r0 < M)
                __stcs((float2*)(C + (size_t)r0 * ldc + col),
                       make_float2(acc[mt][nt][0], acc[mt][nt][1]));
            if (r0 + 8 < M)
                __stcs((float2*)(C + (size_t)(r0 + 8) * ldc + col),
                       make_float2(acc[mt][nt][2], acc[mt][nt][3]));
        }
    }
}

// grid (MT, 2, 2):
//   z=0:        rz combined K=256, j0=y*128, C=g_grz (ldc 256)
//   z=1, y=0:   i_n = agg @ W_comb_n, K=128, C=g_gin
//   z=1, y=1:   h_n = h @ w_hh_n,     K=128, C=g_ghn
__global__ __launch_bounds__(256, 2)
void mma_gemm_fused(const unsigned short* __restrict__ rzh,
                    const unsigned short* __restrict__ rzl,
                    const unsigned short* __restrict__ cnh,
                    const unsigned short* __restrict__ cnl, int M) {
    if (blockIdx.z == 0)
        gemm_tile<4>(g_ah, g_al, g_xh, g_xl, rzh, rzl, g_grz, M, 256, blockIdx.y * 128);
    else if (blockIdx.y == 0)
        gemm_tile<2>(g_ah, g_al, g_ah, g_al, cnh, cnl, g_gin, M, HH, 0);
    else
        gemm_tile<2>(g_xh, g_xl, g_xh, g_xl, g_hn_h, g_hn_l, g_ghn, M, HH, 0);
}

// ---------------- GRU elementwise; optional plane writes; optional fused head ----------------
__global__ void gru_kernel(const float* __restrict__ b_ih, const float* __restrict__ b_hh,
                           int write_planes, int do_lin,
                           const float* __restrict__ lw, const float* __restrict__ lb,
                           float* __restrict__ out_unc) {
    int t = blockIdx.x * 256 + threadIdx.x;
    int n = t >> 5;                       // warp per node
    int lane = t & 31;
    int j = lane * 4;
    size_t rzo = (size_t)n * 256 + j;
    float4 rr = __ldcs((const float4*)(g_grz + rzo));         // i_r + h_r
    float4 zz = __ldcs((const float4*)(g_grz + rzo + 128));   // i_z + h_z
    float4 inn = __ldcs((const float4*)(g_gin + (size_t)n * HH + j));
    float4 hnn = __ldcs((const float4*)(g_ghn + (size_t)n * HH + j));
    float4 bir = __ldg((const float4*)(b_ih + j));
    float4 biz = __ldg((const float4*)(b_ih + 128 + j));
    float4 bin = __ldg((const float4*)(b_ih + 256 + j));
    float4 bhr = __ldg((const float4*)(b_hh + j));
    float4 bhz = __ldg((const float4*)(b_hh + 128 + j));
    float4 bhn = __ldg((const float4*)(b_hh + 256 + j));
    float4 hv = *(const float4*)(g_h + (size_t)n * HH + j);

    float4 out;
#define GRU1(c)                                                            \
    {                                                                      \
        float r = sigf(rr.c + bir.c + bhr.c);                              \
        float z = sigf(zz.c + biz.c + bhz.c);                              \
        float ng = tanhfast(inn.c + bin.c + r * (hnn.c + bhn.c));          \
        out.c = (1.f - z) * ng + z * hv.c;                                 \
    }
    GRU1(x) GRU1(y) GRU1(z) GRU1(w)
#undef GRU1
    *(float4*)(g_h + (size_t)n * HH + j) = out;
    if (write_planes) {
        uint2 hvp, lvp;
        split4(out, hvp, lvp);
        *(uint2*)(g_xh + (size_t)n * HH + j) = hvp;
        *(uint2*)(g_xl + (size_t)n * HH + j) = lvp;
    }
    if (do_lin) {
        float4 a = out;
        a.x = fmaxf(a.x, 0.f); a.y = fmaxf(a.y, 0.f);
        a.z = fmaxf(a.z, 0.f); a.w = fmaxf(a.w, 0.f);
        float4 w = __ldg((const float4*)lw + lane);
        float s = a.x * w.x + a.y * w.y + a.z * w.z + a.w * w.w;
#pragma unroll
        for (int o = 16; o; o >>= 1) s += __shfl_xor_sync(0xffffffffu, s, o);
        if (lane == 0) {
            float v = s + __ldg(lb);
            g_outv[n] = v;
            out_unc[n] = v;
            int b = g_batch[n];
            atomicAdd(&g_gsum[b], v);
            atomicAdd(&g_gcnt[b], 1.f);
        }
    }
}

__global__ void correct_kernel(float* __restrict__ out_corr) {
    int n = blockIdx.x * 256 + threadIdx.x;
    if (n >= NNODES) return;
    int b = g_batch[n];
    out_corr[n] = g_outv[n] - g_gsum[b] / fmaxf(g_gcnt[b], 1.f);
}

// ---------------- launcher ----------------
extern "C" void kernel_launch(void* const* d_in, const int* in_sizes, int n_in,
                              void* d_out, int out_size) {
    const float* x = (const float*)d_in[0];
    const void* edge = d_in[1];
    const void* batch = d_in[2];
    int wi = 3;
    if (in_sizes[3] == 1) wi = 4;
    const float* W0     = (const float*)d_in[wi + 0];
    const float* conv_w = (const float*)d_in[wi + 1];
    const float* w_ih   = (const float*)d_in[wi + 2];
    const float* b_ih   = (const float*)d_in[wi + 3];
    const float* w_hh   = (const float*)d_in[wi + 4];
    const float* b_hh   = (const float*)d_in[wi + 5];
    const float* lin1_w = (const float*)d_in[wi + 6];
    const float* lin1_b = (const float*)d_in[wi + 7];

    float* out = (float*)d_out;
    float* out_corr = out;
    float* out_emb  = out + NNODES;
    float* out_unc  = out + NNODES + (size_t)NNODES * HH;

    cudaFuncSetAttribute(mma_gemm_fused, cudaFuncAttributeMaxDynamicSharedMemorySize,
                         MMA_SMEM);
    cudaFuncSetAttribute(fold_gemm_kernel, cudaFuncAttributeMaxDynamicSharedMemorySize,
                         FOLD_SMEM);

    unsigned short *p_rzh, *p_rzl, *p_cnh, *p_cnl;
    cudaGetSymbolAddress((void**)&p_rzh, g_rz_h);
    cudaGetSymbolAddress((void**)&p_rzl, g_rz_l);
    cudaGetSymbolAddress((void**)&p_cnh, g_cn_h);
    cudaGetSymbolAddress((void**)&p_cnl, g_cn_l);

    // setup
    zero_init_kernel<<<(NNODES + 255) / 256, 256>>>();
    detect_kernel<<<dim3(256, 2), 256>>>((const unsigned int*)edge,
                                         (const unsigned int*)batch);
    convert_edges_kernel<<<(EEDGES + 255) / 256, 256>>>(edge);
    convert_batch_kernel<<<(NNODES + 255) / 256, 256>>>(batch);
    scan1_kernel<<<NSCAN, SCANB>>>();
    scan2_kernel<<<1, 256>>>();
    scan3_kernel<<<NSCAN, SCANB>>>();
    fill_csr_kernel<<<(EEDGES + 255) / 256, 256>>>();
    fold_gemm_kernel<<<dim3(3, 1, LLAYERS), 256, FOLD_SMEM>>>(w_ih, conv_w);
    whh_split_kernel<<<(H3 * HH + 255) / 256, 256>>>(w_hh);

    const int MT = (NNODES + 127) / 128;   // 782
    embed_kernel<<<MT, 256>>>(x, W0, out_emb);

    for (int l = 0; l < LLAYERS; l++) {
        int last = (l == LLAYERS - 1);
        aggregate_kernel<<<NNODES * 32 / 256, 256>>>();
        mma_gemm_fused<<<dim3(MT, 2, 2), 256, MMA_SMEM>>>(
            p_rzh + (size_t)l * 256 * 256, p_rzl + (size_t)l * 256 * 256,
            p_cnh + (size_t)l * HH * HH, p_cnl + (size_t)l * HH * HH, NNODES);
        gru_kernel<<<NNODES * 32 / 256, 256>>>(b_ih, b_hh, !last, last,
                                               lin1_w, lin1_b, out_unc);
    }

    correct_kernel<<<(NNODES + 255) / 256, 256>>>(out_corr);
}

// round 17
// speedup vs baseline: 1.2769x; 1.0081x over previous
#include <cuda_runtime.h>
#include <cuda_bf16.h>
#include <cstdint>

#define NNODES 100000
#define NPAD 100096                     // padded rows (multiple of 128)
#define EEDGES 1600000
#define FF 32
#define HH 128
#define LLAYERS 4
#define GG 64
#define H3 384
#define SCANB 512
#define NSCAN ((NNODES + SCANB - 1) / SCANB)   // 196

// ---------------- scratch (device globals; no allocation) ----------------
__device__ float g_h[(size_t)NNODES * HH];
__device__ float g_grz[(size_t)NNODES * 256];   // combined r,z pre-activations (gi+gh)
__device__ float g_gin[(size_t)NNODES * HH];    // i_n
__device__ float g_ghn[(size_t)NNODES * HH];    // h_n
__device__ float g_outv[NNODES];
__device__ float g_gsum[GG];
__device__ float g_gcnt[GG];
__device__ int   g_src[EEDGES];
__device__ int   g_dst[EEDGES];
__device__ int   g_batch[NNODES];
__device__ int   g_edge_i32;
__device__ int   g_batch_i32;
// CSR
__device__ int   g_deg[NNODES];
__device__ int   g_cur[NNODES];
__device__ int   g_off[NNODES + 1];
__device__ int   g_part[NSCAN];
__device__ int   g_part2[NSCAN];
__device__ int   g_csr_src[EEDGES];

// pre-split bf16 A operands (hi/lo planes), padded rows
__device__ unsigned short g_ah[(size_t)NPAD * HH];   // agg hi
__device__ unsigned short g_al[(size_t)NPAD * HH];   // agg lo
__device__ unsigned short g_xh[(size_t)NPAD * HH];   // h hi
__device__ unsigned short g_xl[(size_t)NPAD * HH];   // h lo

// bf16 split weights (hi/lo), n-major:
// rz combined: [l][col 0..255][k 0..255]; k<128 -> W_comb_rz, k>=128 -> w_hh_rz
__device__ unsigned short g_rz_h[(size_t)LLAYERS * 256 * 256];
__device__ unsigned short g_rz_l[(size_t)LLAYERS * 256 * 256];
// n gates: i_n weights [l][128][128], h_n weights [128][128]
__device__ unsigned short g_cn_h[(size_t)LLAYERS * HH * HH];
__device__ unsigned short g_cn_l[(size_t)LLAYERS * HH * HH];
__device__ unsigned short g_hn_h[HH * HH];
__device__ unsigned short g_hn_l[HH * HH];

// ---------------- math helpers ----------------
__device__ __forceinline__ void pdl_sync() {
#if defined(__CUDA_ARCH__) && __CUDA_ARCH__ >= 900
    cudaGridDependencySynchronize();
#endif
}
__device__ __forceinline__ float sigf(float x) { return 1.f / (1.f + __expf(-x)); }
__device__ __forceinline__ float tanhfast(float x) {
    float ax = fabsf(x);
    float e = __expf(-2.f * ax);
    float t = (1.f - e) / (1.f + e);
    return copysignf(t, x);
}
__device__ __forceinline__ void fma2(unsigned long long& d, unsigned long long a,
                                     unsigned long long b) {
    asm("fma.rn.f32x2 %0, %1, %2, %3;" : "=l"(d) : "l"(a), "l"(b), "l"(d));
}
__device__ __forceinline__ unsigned long long pack_dup(float x) {
    unsigned long long r;
    asm("mov.b64 %0, {%1, %1};" : "=l"(r) : "f"(x));
    return r;
}
__device__ __forceinline__ float2 unpack2(unsigned long long v) {
    float2 r;
    asm("mov.b64 {%0, %1}, %2;" : "=f"(r.x), "=f"(r.y) : "l"(v));
    return r;
}
__device__ __forceinline__ void split1(float a, unsigned short& h, unsigned short& l) {
    __nv_bfloat16 ha = __float2bfloat16_rn(a);
    float ra = a - __bfloat162float(ha);
    __nv_bfloat16 la = __float2bfloat16_rn(ra);
    h = __bfloat16_as_ushort(ha);
    l = __bfloat16_as_ushort(la);
}
__device__ __forceinline__ void split2(float a, float b, unsigned& h, unsigned& l) {
    unsigned short ha, la, hb, lb;
    split1(a, ha, la);
    split1(b, hb, lb);
    h = (unsigned)ha | ((unsigned)hb << 16);
    l = (unsigned)la | ((unsigned)lb << 16);
}
__device__ __forceinline__ void split4(float4 v, uint2& h, uint2& l) {
    split2(v.x, v.y, h.x, l.x);
    split2(v.z, v.w, h.y, l.y);
}
__device__ __forceinline__ void ldm4(unsigned r[4], uint32_t addr) {
    asm volatile("ldmatrix.sync.aligned.m8n8.x4.shared.b16 {%0,%1,%2,%3}, [%4];\n"
                 : "=r"(r[0]), "=r"(r[1]), "=r"(r[2]), "=r"(r[3])
                 : "r"(addr));
}
__device__ __forceinline__ void mma16816(float* c, const unsigned a[4],
                                         unsigned b0, unsigned b1) {
    asm("mma.sync.aligned.m16n8k16.row.col.f32.bf16.bf16.f32 "
        "{%0,%1,%2,%3}, {%4,%5,%6,%7}, {%8,%9}, {%0,%1,%2,%3};\n"
        : "+f"(c[0]), "+f"(c[1]), "+f"(c[2]), "+f"(c[3])
        : "r"(a[0]), "r"(a[1]), "r"(a[2]), "r"(a[3]), "r"(b0), "r"(b1));
}

// ---------------- setup kernels ----------------
__global__ void zero_init_kernel() {
    int i = blockIdx.x * 256 + threadIdx.x;
    if (i < NNODES) { g_deg[i] = 0; g_cur[i] = 0; }
    if (i < GG) { g_gsum[i] = 0.f; g_gcnt[i] = 0.f; }
    if (i == 0) { g_edge_i32 = 0; g_batch_i32 = 0; }
}
__global__ void detect_kernel(const unsigned int* __restrict__ pe,
                              const unsigned int* __restrict__ pb) {
    int which = blockIdx.y;
    const unsigned int* p = which ? pb : pe;
    long long nwords = which ? (long long)NNODES : 2LL * EEDGES;
    long long i = 1 + 2LL * (blockIdx.x * (long long)blockDim.x + threadIdx.x);
    long long stride = 2LL * gridDim.x * blockDim.x;
    int found = 0;
    for (; i < nwords; i += stride)
        if (p[i]) { found = 1; break; }
    if (found) { if (which == 0) g_edge_i32 = 1; else g_batch_i32 = 1; }
}
__global__ void convert_edges_kernel(const void* __restrict__ e) {
    int i = blockIdx.x * 256 + threadIdx.x;
    if (i >= EEDGES) return;
    int s, d;
    if (g_edge_i32) {
        const int* p = (const int*)e;
        s = __ldcs(p + i); d = __ldcs(p + EEDGES + i);
    } else {
        const long long* p = (const long long*)e;
        s = (int)__ldcs(p + i); d = (int)__ldcs(p + EEDGES + i);
    }
    g_src[i] = s;
    g_dst[i] = d;
    atomicAdd(&g_deg[d], 1);
}
__global__ void convert_batch_kernel(const void* __restrict__ b) {
    int i = blockIdx.x * 256 + threadIdx.x;
    if (i >= NNODES) return;
    if (g_batch_i32) g_batch[i] = ((const int*)b)[i];
    else             g_batch[i] = (int)((const long long*)b)[i];
}

// ---------------- scan (exclusive prefix over degrees) ----------------
__global__ void scan1_kernel() {
    __shared__ int s[SCANB];
    int t = threadIdx.x;
    int i = blockIdx.x * SCANB + t;
    int v = (i < NNODES) ? g_deg[i] : 0;
    s[t] = v;
    __syncthreads();
#pragma unroll
    for (int o = 1; o < SCANB; o <<= 1) {
        int x = (t >= o) ? s[t - o] : 0;
        __syncthreads();
        s[t] += x;
        __syncthreads();
    }
    if (i < NNODES) g_off[i] = s[t] - v;
    if (t == SCANB - 1) g_part[blockIdx.x] = s[t];
}
__global__ void scan2_kernel() {
    __shared__ int s[256];
    int t = threadIdx.x;
    int v = (t < NSCAN) ? g_part[t] : 0;
    s[t] = v;
    __syncthreads();
#pragma unroll
    for (int o = 1; o < 256; o <<= 1) {
        int x = (t >= o) ? s[t - o] : 0;
        __syncthreads();
        s[t] += x;
        __syncthreads();
    }
    if (t < NSCAN) g_part2[t] = s[t] - v;
}
__global__ void scan3_kernel() {
    int i = blockIdx.x * SCANB + threadIdx.x;
    if (i < NNODES) g_off[i] += g_part2[blockIdx.x];
    if (i == 0) g_off[NNODES] = EEDGES;
}
__global__ void fill_csr_kernel() {
    int i = blockIdx.x * 256 + threadIdx.x;
    if (i >= EEDGES) return;
    int d = g_dst[i];
    int p = atomicAdd(&g_cur[d], 1);
    g_csr_src[g_off[d] + p] = g_src[i];
}

// ---------------- fold GEMM: W_comb = w_ih x conv_w; epilogue splits + routes ----------------
#define FOLD_SMEM (2 * 128 * 128 * 4)
__global__ void fold_gemm_kernel(const float* __restrict__ A,
                                 const float* __restrict__ Bbase) {
    const float* B = Bbase + (size_t)blockIdx.z * HH * HH;
    const int l = blockIdx.z;
    extern __shared__ float smf[];
    float* aT = smf;
    float* ws = smf + 128 * 128;
    int m0 = blockIdx.x * 128;
    int tid = threadIdx.x;
    {
        int i = tid >> 1;
        int kq0 = (tid & 1) * 16;
        const float4* Ar = (const float4*)(A + (size_t)(m0 + i) * 128);
#pragma unroll
        for (int q = 0; q < 16; q++) {
            int k4 = kq0 + q;
            float4 v = Ar[k4];
            aT[(k4 * 4 + 0) * 128 + i] = v.x; aT[(k4 * 4 + 1) * 128 + i] = v.y;
            aT[(k4 * 4 + 2) * 128 + i] = v.z; aT[(k4 * 4 + 3) * 128 + i] = v.w;
        }
    }
    {
        int k = tid >> 1;
        int kq0 = (tid & 1) * 16;
        const float4* Br = (const float4*)(B + (size_t)k * 128);
#pragma unroll
        for (int q = 0; q < 16; q++) {
            int k4 = kq0 + q;
            float4 v = Br[k4];
            ws[(k4 * 4 + 0) * 128 + k] = v.x; ws[(k4 * 4 + 1) * 128 + k] = v.y;
            ws[(k4 * 4 + 2) * 128 + k] = v.z; ws[(k4 * 4 + 3) * 128 + k] = v.w;
        }
    }
    __syncthreads();

    int tx = tid & 15, ty = tid >> 4;
    unsigned long long acc[8][4];
#pragma unroll
    for (int i = 0; i < 8; i++)
#pragma unroll
        for (int j = 0; j < 4; j++) acc[i][j] = 0ull;

    const float* aBase = aT + ty * 8;
    const float* bBase = ws + tx * 8;
#pragma unroll 4
    for (int k = 0; k < 128; k++) {
        float4 a0 = *(const float4*)(aBase + k * 128);
        float4 a1 = *(const float4*)(aBase + k * 128 + 4);
        const unsigned long long* bp = (const unsigned long long*)(bBase + k * 128);
        unsigned long long b0 = bp[0], b1 = bp[1], b2 = bp[2], b3 = bp[3];
        float av[8] = {a0.x, a0.y, a0.z, a0.w, a1.x, a1.y, a1.z, a1.w};
#pragma unroll
        for (int i = 0; i < 8; i++) {
            unsigned long long a2 = pack_dup(av[i]);
            fma2(acc[i][0], a2, b0); fma2(acc[i][1], a2, b1);
            fma2(acc[i][2], a2, b2); fma2(acc[i][3], a2, b3);
        }
    }
#pragma unroll
    for (int i = 0; i < 8; i++) {
        int row = m0 + ty * 8 + i;          // gate-output index 0..383
        float vv[8];
        float2 v0 = unpack2(acc[i][0]), v1 = unpack2(acc[i][1]);
        float2 v2 = unpack2(acc[i][2]), v3 = unpack2(acc[i][3]);
        vv[0] = v0.x; vv[1] = v0.y; vv[2] = v1.x; vv[3] = v1.y;
        vv[4] = v2.x; vv[5] = v2.y; vv[6] = v3.x; vv[7] = v3.y;
        unsigned short hs[8], ls[8];
#pragma unroll
        for (int q = 0; q < 8; q++) split1(vv[q], hs[q], ls[q]);
        if (row < 256) {                    // r,z gates -> rz combined, k slot [0,128)
            size_t off = ((size_t)l * 256 + row) * 256 + tx * 8;
#pragma unroll
            for (int q = 0; q < 8; q++) { g_rz_h[off + q] = hs[q]; g_rz_l[off + q] = ls[q]; }
        } else {                            // n gate -> cn
            size_t off = ((size_t)l * HH + (row - 256)) * HH + tx * 8;
#pragma unroll
            for (int q = 0; q < 8; q++) { g_cn_h[off + q] = hs[q]; g_cn_l[off + q] = ls[q]; }
        }
    }
}

__global__ void whh_split_kernel(const float* __restrict__ whh) {
    int idx = blockIdx.x * 256 + threadIdx.x;
    if (idx >= H3 * HH) return;
    int o = idx >> 7;
    int k = idx & 127;
    unsigned short h, lo;
    split1(whh[idx], h, lo);
    if (o < 256) {
#pragma unroll
        for (int l = 0; l < LLAYERS; l++) {
            size_t off = ((size_t)l * 256 + o) * 256 + 128 + k;
            g_rz_h[off] = h; g_rz_l[off] = lo;
        }
    } else {
        size_t off = (size_t)(o - 256) * HH + k;
        g_hn_h[off] = h; g_hn_l[off] = lo;
    }
}

// ---------------- embed: h = sigmoid(x @ W0^T); writes h fp32 + planes ----------------
__global__ void embed_kernel(const float* __restrict__ x, const float* __restrict__ W0,
                             float* __restrict__ out_emb) {
    __shared__ float xT[FF * 128];
    __shared__ float wT[FF * 128];
    int m0 = blockIdx.x * 128;
    int tid = threadIdx.x;
    {
        int i = tid >> 1;
        int q0 = (tid & 1) * 4;
        bool ok = (m0 + i) < NNODES;
        const float4* xr = (const float4*)(x + (size_t)(m0 + i) * FF);
        const float4* wr = (const float4*)(W0 + (size_t)i * FF);
#pragma unroll
        for (int q = 0; q < 4; q++) {
            float4 v = ok ? xr[q0 + q] : make_float4(0.f, 0.f, 0.f, 0.f);
            int k = (q0 + q) * 4;
            xT[(k + 0) * 128 + i] = v.x; xT[(k + 1) * 128 + i] = v.y;
            xT[(k + 2) * 128 + i] = v.z; xT[(k + 3) * 128 + i] = v.w;
        }
#pragma unroll
        for (int q = 0; q < 4; q++) {
            float4 v = wr[q0 + q];
            int k = (q0 + q) * 4;
            wT[(k + 0) * 128 + i] = v.x; wT[(k + 1) * 128 + i] = v.y;
            wT[(k + 2) * 128 + i] = v.z; wT[(k + 3) * 128 + i] = v.w;
        }
    }
    __syncthreads();
    int tx = tid & 15, ty = tid >> 4;
    unsigned long long acc[8][4];
#pragma unroll
    for (int i = 0; i < 8; i++)
#pragma unroll
        for (int j = 0; j < 4; j++) acc[i][j] = 0ull;

    const float* aBase = xT + ty * 8;
    const float* bBase = wT + tx * 8;
#pragma unroll 4
    for (int k = 0; k < FF; k++) {
        float4 a0 = *(const float4*)(aBase + k * 128);
        float4 a1 = *(const float4*)(aBase + k * 128 + 4);
        const unsigned long long* bp = (const unsigned long long*)(bBase + k * 128);
        unsigned long long b0 = bp[0], b1 = bp[1], b2 = bp[2], b3 = bp[3];
        float av[8] = {a0.x, a0.y, a0.z, a0.w, a1.x, a1.y, a1.z, a1.w};
#pragma unroll
        for (int i = 0; i < 8; i++) {
            unsigned long long a2 = pack_dup(av[i]);
            fma2(acc[i][0], a2, b0); fma2(acc[i][1], a2, b1);
            fma2(acc[i][2], a2, b2); fma2(acc[i][3], a2, b3);
        }
    }
#pragma unroll
    for (int i = 0; i < 8; i++) {
        int row = m0 + ty * 8 + i;
        if (row < NNODES) {
            float2 v0 = unpack2(acc[i][0]), v1 = unpack2(acc[i][1]);
            float2 v2 = unpack2(acc[i][2]), v3 = unpack2(acc[i][3]);
            float4 o0 = make_float4(sigf(v0.x), sigf(v0.y), sigf(v1.x), sigf(v1.y));
            float4 o1 = make_float4(sigf(v2.x), sigf(v2.y), sigf(v3.x), sigf(v3.y));
            size_t off = (size_t)row * HH + tx * 8;
            *(float4*)(g_h + off) = o0;     *(float4*)(g_h + off + 4) = o1;
            *(float4*)(out_emb + off) = o0; *(float4*)(out_emb + off + 4) = o1;
            uint2 hh0, ll0, hh1, ll1;
            split4(o0, hh0, ll0);
            split4(o1, hh1, ll1);
            *(uint4*)(g_xh + off) = make_uint4(hh0.x, hh0.y, hh1.x, hh1.y);
            *(uint4*)(g_xl + off) = make_uint4(ll0.x, ll0.y, ll1.x, ll1.y);
        }
    }
}

// ---------------- CSR aggregation -> pre-split bf16 planes (unroll 4, PDL) ----------------
__global__ void aggregate_kernel() {
    int w = (blockIdx.x * 256 + threadIdx.x) >> 5;
    int lane = threadIdx.x & 31;
    // prologue: CSR offsets are setup data (no dependency on prior gru)
    int e0 = 0, e1 = 0;
    if (w < NNODES) { e0 = g_off[w]; e1 = g_off[w + 1]; }
    pdl_sync();                              // wait for gru's h writes
    if (w >= NNODES) return;
    float4 a = make_float4(0.f, 0.f, 0.f, 0.f);
    int e = e0;
    for (; e + 4 <= e1; e += 4) {
        int s0 = __ldcs(g_csr_src + e),     s1 = __ldcs(g_csr_src + e + 1);
        int s2 = __ldcs(g_csr_src + e + 2), s3 = __ldcs(g_csr_src + e + 3);
        float4 v0 = __ldg((const float4*)(g_h + (size_t)s0 * HH) + lane);
        float4 v1 = __ldg((const float4*)(g_h + (size_t)s1 * HH) + lane);
        float4 v2 = __ldg((const float4*)(g_h + (size_t)s2 * HH) + lane);
        float4 v3 = __ldg((const float4*)(g_h + (size_t)s3 * HH) + lane);
        a.x += (v0.x + v1.x) + (v2.x + v3.x);
        a.y += (v0.y + v1.y) + (v2.y + v3.y);
        a.z += (v0.z + v1.z) + (v2.z + v3.z);
        a.w += (v0.w + v1.w) + (v2.w + v3.w);
    }
    for (; e < e1; e++) {
        int s0 = __ldcs(g_csr_src + e);
        float4 v0 = __ldg((const float4*)(g_h + (size_t)s0 * HH) + lane);
        a.x += v0.x; a.y += v0.y; a.z += v0.z; a.w += v0.w;
    }
    uint2 hv, lv;
    split4(a, hv, lv);
    *((uint2*)(g_ah + (size_t)w * HH) + lane) = hv;
    *((uint2*)(g_al + (size_t)w * HH) + lane) = lv;
}

// ---------------- tensor-core GEMM tile (bf16 split-3), 128x128, K=KCH*64 ----------------
#define SAW2 72
#define MMA_SMEM (4 * 128 * SAW2 * 2)

template <int KCH>
__device__ __forceinline__ void gemm_tile(const unsigned short* __restrict__ A0h,
                                          const unsigned short* __restrict__ A0l,
                                          const unsigned short* __restrict__ A1h,
                                          const unsigned short* __restrict__ A1l,
                                          const unsigned short* __restrict__ Bh,
                                          const unsigned short* __restrict__ Bl,
                                          float* __restrict__ C, int M, int ldc, int j0) {
    extern __shared__ unsigned short smx[];
    const int tid = threadIdx.x;
    const int m0 = blockIdx.x * 128;
    const int lane = tid & 31, wid = tid >> 5;
    const int wm = wid >> 2, wn = wid & 3;

    float acc[4][4][4];
#pragma unroll
    for (int a = 0; a < 4; a++)
#pragma unroll
        for (int b = 0; b < 4; b++)
#pragma unroll
            for (int c = 0; c < 4; c++) acc[a][b][c] = 0.f;

    uint32_t sbase = (uint32_t)__cvta_generic_to_shared(smx);
    const uint32_t oAh = 0;
    const uint32_t oAl = 128 * SAW2 * 2;
    const uint32_t oBh = 2 * 128 * SAW2 * 2;
    const uint32_t oBl = 3 * 128 * SAW2 * 2;
    unsigned short* sAh = smx;
    unsigned short* sAl = smx + 128 * SAW2;
    unsigned short* sBh = smx + 2 * 128 * SAW2;
    unsigned short* sBl = smx + 3 * 128 * SAW2;

    const int ai = tid >> 1;
    const int half = tid & 1;
    const size_t aoff = (size_t)(m0 + ai) * HH;
    const size_t boff = (size_t)(j0 + ai) * (KCH * 64);
    const uint4* a0h = (const uint4*)(A0h + aoff);
    const uint4* a0l = (const uint4*)(A0l + aoff);
    const uint4* a1h = (const uint4*)(A1h + aoff);
    const uint4* a1l = (const uint4*)(A1l + aoff);
    const uint4* brh = (const uint4*)(Bh + boff);
    const uint4* brl = (const uint4*)(Bl + boff);

    pdl_sync();   // wait for aggregate's plane writes before reading A

#pragma unroll
    for (int ch = 0; ch < KCH; ch++) {
        const uint4* sh = (KCH == 2 || ch < 2) ? a0h : a1h;
        const uint4* sl = (KCH == 2 || ch < 2) ? a0l : a1l;
        const int ach = ch & 1;
        uint4* dAh = (uint4*)(sAh + ai * SAW2 + half * 32);
        uint4* dAl = (uint4*)(sAl + ai * SAW2 + half * 32);
        uint4* dBh = (uint4*)(sBh + ai * SAW2 + half * 32);
        uint4* dBl = (uint4*)(sBl + ai * SAW2 + half * 32);
#pragma unroll
        for (int q = 0; q < 4; q++) {
            dAh[q] = sh[ach * 8 + half * 4 + q];
            dAl[q] = sl[ach * 8 + half * 4 + q];
            dBh[q] = brh[ch * 8 + half * 4 + q];
            dBl[q] = brl[ch * 8 + half * 4 + q];
        }
        __syncthreads();

#pragma unroll
        for (int ks = 0; ks < 4; ks++) {
            unsigned bh[2][4], bl[2][4];
#pragma unroll
            for (int np = 0; np < 2; np++) {
                uint32_t off = ((wn * 32 + np * 16 + (lane & 15)) * SAW2 +
                                ks * 16 + (lane >> 4) * 8) * 2;
                ldm4(bh[np], sbase + oBh + off);
                ldm4(bl[np], sbase + oBl + off);
            }
#pragma unroll
            for (int mt = 0; mt < 4; mt++) {
                unsigned a_h[4], a_l[4];
                uint32_t off = ((wm * 64 + mt * 16 + (lane & 15)) * SAW2 +
                                ks * 16 + (lane >> 4) * 8) * 2;
                ldm4(a_h, sbase + oAh + off);
                ldm4(a_l, sbase + oAl + off);
#pragma unroll
                for (int nt = 0; nt < 4; nt++) {
                    int np = nt >> 1, od = nt & 1;
                    float* c = acc[mt][nt];
                    mma16816(c, a_h, bh[np][od], bh[np][2 + od]);
                    mma16816(c, a_h, bl[np][od], bl[np][2 + od]);
                    mma16816(c, a_l, bh[np][od], bh[np][2 + od]);
                }
            }
        }
        __syncthreads();
    }

    // streaming epilogue (gates read exactly once by gru)
#pragma unroll
    for (int mt = 0; mt < 4; mt++) {
        int r0 = m0 + wm * 64 + mt * 16 + (lane >> 2);
#pragma unroll
        for (int nt = 0; nt < 4; nt++) {
            int col = j0 + wn * 32 + nt * 8 + (lane & 3) * 2;
            if (r0 < M)
                __stcs((float2*)(C + (size_t)r0 * ldc + col),
                       make_float2(acc[mt][nt][0], acc[mt][nt][1]));
            if (r0 + 8 < M)
                __stcs((float2*)(C + (size_t)(r0 + 8) * ldc + col),
                       make_float2(acc[mt][nt][2], acc[mt][nt][3]));
        }
    }
}

// grid (MT, 2, 2):
//   z=0:        rz combined K=256, j0=y*128, C=g_grz (ldc 256)
//   z=1, y=0:   i_n = agg @ W_comb_n, K=128, C=g_gin
//   z=1, y=1:   h_n = h @ w_hh_n,     K=128, C=g_ghn
__global__ __launch_bounds__(256, 2)
void mma_gemm_fused(const unsigned short* __restrict__ rzh,
                    const unsigned short* __restrict__ rzl,
                    const unsigned short* __restrict__ cnh,
                    const unsigned short* __restrict__ cnl, int M) {
    if (blockIdx.z == 0)
        gemm_tile<4>(g_ah, g_al, g_xh, g_xl, rzh, rzl, g_grz, M, 256, blockIdx.y * 128);
    else if (blockIdx.y == 0)
        gemm_tile<2>(g_ah, g_al, g_ah, g_al, cnh, cnl, g_gin, M, HH, 0);
    else
        gemm_tile<2>(g_xh, g_xl, g_xh, g_xl, g_hn_h, g_hn_l, g_ghn, M, HH, 0);
}

// ---------------- GRU elementwise; optional plane writes; optional fused head (PDL) ----------------
__global__ void gru_kernel(const float* __restrict__ b_ih, const float* __restrict__ b_hh,
                           int write_planes, int do_lin,
                           const float* __restrict__ lw, const float* __restrict__ lb,
                           float* __restrict__ out_unc) {
    int t = blockIdx.x * 256 + threadIdx.x;
    int n = t >> 5;                       // warp per node
    int lane = t & 31;
    int j = lane * 4;
    // prologue: biases are kernel inputs (no dependency on the GEMM)
    float4 bir = __ldg((const float4*)(b_ih + j));
    float4 biz = __ldg((const float4*)(b_ih + 128 + j));
    float4 bin = __ldg((const float4*)(b_ih + 256 + j));
    float4 bhr = __ldg((const float4*)(b_hh + j));
    float4 bhz = __ldg((const float4*)(b_hh + 128 + j));
    float4 bhn = __ldg((const float4*)(b_hh + 256 + j));
    pdl_sync();                           // wait for GEMM's gate writes
    size_t rzo = (size_t)n * 256 + j;
    float4 rr = __ldcs((const float4*)(g_grz + rzo));         // i_r + h_r
    float4 zz = __ldcs((const float4*)(g_grz + rzo + 128));   // i_z + h_z
    float4 inn = __ldcs((const float4*)(g_gin + (size_t)n * HH + j));
    float4 hnn = __ldcs((const float4*)(g_ghn + (size_t)n * HH + j));
    float4 hv = *(const float4*)(g_h + (size_t)n * HH + j);

    float4 out;
#define GRU1(c)                                                            \
    {                                                                      \
        float r = sigf(rr.c + bir.c + bhr.c);                              \
        float z = sigf(zz.c + biz.c + bhz.c);                              \
        float ng = tanhfast(inn.c + bin.c + r * (hnn.c + bhn.c));          \
        out.c = (1.f - z) * ng + z * hv.c;                                 \
    }
    GRU1(x) GRU1(y) GRU1(z) GRU1(w)
#undef GRU1
    *(float4*)(g_h + (size_t)n * HH + j) = out;
    if (write_planes) {
        uint2 hvp, lvp;
        split4(out, hvp, lvp);
        *(uint2*)(g_xh + (size_t)n * HH + j) = hvp;
        *(uint2*)(g_xl + (size_t)n * HH + j) = lvp;
    }
    if (do_lin) {
        float4 a = out;
        a.x = fmaxf(a.x, 0.f); a.y = fmaxf(a.y, 0.f);
        a.z = fmaxf(a.z, 0.f); a.w = fmaxf(a.w, 0.f);
        float4 w = __ldg((const float4*)lw + lane);
        float s = a.x * w.x + a.y * w.y + a.z * w.z + a.w * w.w;
#pragma unroll
        for (int o = 16; o; o >>= 1) s += __shfl_xor_sync(0xffffffffu, s, o);
        if (lane == 0) {
            float v = s + __ldg(lb);
            g_outv[n] = v;
            out_unc[n] = v;
            int b = g_batch[n];
            atomicAdd(&g_gsum[b], v);
            atomicAdd(&g_gcnt[b], 1.f);
        }
    }
}

__global__ void correct_kernel(float* __restrict__ out_corr) {
    int n = blockIdx.x * 256 + threadIdx.x;
    pdl_sync();                           // wait for gru's gsum/gcnt atomics
    if (n >= NNODES) return;
    int b = g_batch[n];
    out_corr[n] = g_outv[n] - g_gsum[b] / fmaxf(g_gcnt[b], 1.f);
}

// ---------------- launcher ----------------
template <typename F, typename... Args>
static void launch_pdl(F f, dim3 grid, dim3 block, size_t smem, Args... args) {
    cudaLaunchConfig_t cfg = {};
    cfg.gridDim = grid;
    cfg.blockDim = block;
    cfg.dynamicSmemBytes = smem;
    cfg.stream = 0;
    cudaLaunchAttribute at[1];
    at[0].id = cudaLaunchAttributeProgrammaticStreamSerialization;
    at[0].val.programmaticStreamSerializationAllowed = 1;
    cfg.attrs = at;
    cfg.numAttrs = 1;
    cudaLaunchKernelEx(&cfg, f, args...);
}

extern "C" void kernel_launch(void* const* d_in, const int* in_sizes, int n_in,
                              void* d_out, int out_size) {
    const float* x = (const float*)d_in[0];
    const void* edge = d_in[1];
    const void* batch = d_in[2];
    int wi = 3;
    if (in_sizes[3] == 1) wi = 4;
    const float* W0     = (const float*)d_in[wi + 0];
    const float* conv_w = (const float*)d_in[wi + 1];
    const float* w_ih   = (const float*)d_in[wi + 2];
    const float* b_ih   = (const float*)d_in[wi + 3];
    const float* w_hh   = (const float*)d_in[wi + 4];
    const float* b_hh   = (const float*)d_in[wi + 5];
    const float* lin1_w = (const float*)d_in[wi + 6];
    const float* lin1_b = (const float*)d_in[wi + 7];

    float* out = (float*)d_out;
    float* out_corr = out;
    float* out_emb  = out + NNODES;
    float* out_unc  = out + NNODES + (size_t)NNODES * HH;

    cudaFuncSetAttribute(mma_gemm_fused, cudaFuncAttributeMaxDynamicSharedMemorySize,
                         MMA_SMEM);
    cudaFuncSetAttribute(fold_gemm_kernel, cudaFuncAttributeMaxDynamicSharedMemorySize,
                         FOLD_SMEM);

    unsigned short *p_rzh, *p_rzl, *p_cnh, *p_cnl;
    cudaGetSymbolAddress((void**)&p_rzh, g_rz_h);
    cudaGetSymbolAddress((void**)&p_rzl, g_rz_l);
    cudaGetSymbolAddress((void**)&p_cnh, g_cn_h);
    cudaGetSymbolAddress((void**)&p_cnl, g_cn_l);

    // setup (normal launches)
    zero_init_kernel<<<(NNODES + 255) / 256, 256>>>();
    detect_kernel<<<dim3(256, 2), 256>>>((const unsigned int*)edge,
                                         (const unsigned int*)batch);
    convert_edges_kernel<<<(EEDGES + 255) / 256, 256>>>(edge);
    convert_batch_kernel<<<(NNODES + 255) / 256, 256>>>(batch);
    scan1_kernel<<<NSCAN, SCANB>>>();
    scan2_kernel<<<1, 256>>>();
    scan3_kernel<<<NSCAN, SCANB>>>();
    fill_csr_kernel<<<(EEDGES + 255) / 256, 256>>>();
    fold_gemm_kernel<<<dim3(3, 1, LLAYERS), 256, FOLD_SMEM>>>(w_ih, conv_w);
    whh_split_kernel<<<(H3 * HH + 255) / 256, 256>>>(w_hh);

    const int MT = (NNODES + 127) / 128;   // 782
    embed_kernel<<<MT, 256>>>(x, W0, out_emb);

    for (int l = 0; l < LLAYERS; l++) {
        int last = (l == LLAYERS - 1);
        launch_pdl(aggregate_kernel, dim3(NNODES * 32 / 256), dim3(256), 0);
        launch_pdl(mma_gemm_fused, dim3(MT, 2, 2), dim3(256), (size_t)MMA_SMEM,
                   (const unsigned short*)(p_rzh + (size_t)l * 256 * 256),
                   (const unsigned short*)(p_rzl + (size_t)l * 256 * 256),
                   (const unsigned short*)(p_cnh + (size_t)l * HH * HH),
                   (const unsigned short*)(p_cnl + (size_t)l * HH * HH), (int)NNODES);
        launch_pdl(gru_kernel, dim3(NNODES * 32 / 256), dim3(256), 0,
                   b_ih, b_hh, (int)!last, (int)last, lin1_w, lin1_b, out_unc);
    }

    launch_pdl(correct_kernel, dim3((NNODES + 255) / 256), dim3(256), 0, out_corr);
}